// round 4
// baseline (speedup 1.0000x reference)
#include <cuda_runtime.h>
#include <cstdint>

#define IN_DIM   4096
#define OUT_DIM  1024
#define N_ROWS   16384
#define MAX_E    128           // padded entries per row (E[nnz]=40, +pad<=12, 14-sigma safe)
#define CHUNK    1024          // K-chunk columns
#define NCHUNK   4
#define TILE_N   32            // x rows per CTA
#define XSTRIDE  1025          // floats; 1025 % 32 == 1 -> bank = n + idx (conflict-free)
#define SMEM_FLOATS (TILE_N * XSTRIDE)
#define SMEM_BYTES  (SMEM_FLOATS * 4)
#define THREADS  512

// Scratch in device globals (no allocations allowed)
// entry uint32 = local_byte_offset (col%1024)*4, <=4092; dummy = 4096 (zeroed pad slot)
//              | sign << 31
__device__ uint32_t g_ents[OUT_DIM * MAX_E];
__device__ uint32_t g_off[OUT_DIM];   // packed uint8 padded ends: s1|s2<<8|s3<<16|s4<<24
__device__ float    g_mag;

// ---------------------------------------------------------------------------
// Kernel 1: build padded per-chunk CSR. One warp per output row.
// Deterministic (ballot/popc compaction in column order).
// ---------------------------------------------------------------------------
__global__ void __launch_bounds__(256) build_csr(const float* __restrict__ Phi) {
    const int row  = blockIdx.x * (blockDim.x >> 5) + (threadIdx.x >> 5);
    const int lane = threadIdx.x & 31;
    if (row >= OUT_DIM) return;

    const float* prow = Phi + (size_t)row * IN_DIM;
    uint32_t* erow = g_ents + row * MAX_E;

    int cur = 0;             // warp-uniform running padded position
    uint32_t packed = 0;
    for (int k = 0; k < NCHUNK; ++k) {
        for (int c0 = k * CHUNK; c0 < (k + 1) * CHUNK; c0 += 32) {
            float v = prow[c0 + lane];
            unsigned m = __ballot_sync(0xffffffffu, v != 0.0f);
            if (v != 0.0f) {
                int pos = cur + __popc(m & ((1u << lane) - 1u));
                if (pos < MAX_E) {
                    uint32_t ent = ((unsigned)((c0 + lane) & (CHUNK - 1)) << 2) |
                                   ((__float_as_uint(v) & 0x80000000u));
                    erow[pos] = ent;
                }
                g_mag = fabsf(v);  // same value from every writer (benign)
            }
            cur += __popc(m);
        }
        // pad segment to multiple of 4 with dummies -> read zeroed slot (byteoff 4096)
        int pad = (4 - (cur & 3)) & 3;
        if (lane < pad && (cur + lane) < MAX_E) erow[cur + lane] = CHUNK * 4;
        cur += pad;
        if (cur > MAX_E) cur = MAX_E;  // paranoia; statistically unreachable
        packed |= ((uint32_t)cur & 0xFFu) << (8 * k);
    }
    if (lane == 0) g_off[row] = packed;
}

// ---------------------------------------------------------------------------
// Kernel 2: out = x @ Phi.T.
// CTA: 32 x-rows. Warp lanes = the 32 rows; each warp sweeps 64 output rows r.
// Gathers are warp-uniform-entry, conflict-free LDS. K chunked 4x1024.
// ---------------------------------------------------------------------------
__global__ void __launch_bounds__(THREADS, 1) jl_main(const float* __restrict__ x,
                                                      float* __restrict__ out) {
    extern __shared__ float xs[];
    const int tid  = threadIdx.x;
    const int lane = tid & 31;       // n within tile
    const int w    = tid >> 5;       // warp 0..15, owns r = w*64 .. w*64+63
    const int n0   = blockIdx.x * TILE_N;

    const unsigned magbits = __float_as_uint(g_mag);
    const char* bp = (const char*)xs + lane * (XSTRIDE * 4);  // lane's row base

    float acc[64];
    #pragma unroll
    for (int i = 0; i < 64; ++i) acc[i] = 0.0f;

    const float4* x4 = (const float4*)x;

    for (int k = 0; k < NCHUNK; ++k) {
        if (k) __syncthreads();   // xs reuse across chunks
        // Stage 32 rows x 1024 cols, coalesced float4 reads, scalar smem stores
        #pragma unroll 4
        for (int i = tid; i < TILE_N * (CHUNK / 4); i += THREADS) {
            int row = i >> 8;                 // CHUNK/4 = 256 float4 per row
            int c4  = i & 255;
            float4 v = x4[(size_t)(n0 + row) * (IN_DIM / 4) + k * (CHUNK / 4) + c4];
            float* d = &xs[row * XSTRIDE + (c4 << 2)];
            d[0] = v.x; d[1] = v.y; d[2] = v.z; d[3] = v.w;
        }
        if (tid < TILE_N) xs[tid * XSTRIDE + CHUNK] = 0.0f;  // dummy-entry target
        __syncthreads();

        #pragma unroll
        for (int rr = 0; rr < 64; ++rr) {
            const int r = w * 64 + rr;
            const uint32_t offw = g_off[r];
            const int s = (int)(((offw << 8) >> (8 * k)) & 0xFFu);  // k==0 -> 0
            const int e = (int)((offw >> (8 * k)) & 0xFFu);
            const uint32_t* er = g_ents + (r << 7);

            float a = acc[rr];
            for (int j = s; j < e; j += 4) {
                uint4 q = *(const uint4*)(er + j);
                #define JL_E(ew) {                                              \
                    float xv = *(const float*)(bp + ((ew) & 0xFFFFu));          \
                    float vv = __uint_as_float(magbits ^ ((ew) & 0x80000000u)); \
                    a = fmaf(xv, vv, a); }
                JL_E(q.x) JL_E(q.y) JL_E(q.z) JL_E(q.w)
                #undef JL_E
            }
            acc[rr] = a;
        }
    }

    // Stage outputs in smem (conflict-free: bank = n + r), then coalesced store
    __syncthreads();
    #pragma unroll
    for (int rr = 0; rr < 64; ++rr)
        xs[lane * XSTRIDE + w * 64 + rr] = acc[rr];
    __syncthreads();
    #pragma unroll 4
    for (int i = tid; i < TILE_N * OUT_DIM; i += THREADS) {
        int row = i >> 10;
        int c   = i & 1023;
        out[(size_t)(n0 + row) * OUT_DIM + c] = xs[row * XSTRIDE + c];
    }
}

// ---------------------------------------------------------------------------
extern "C" void kernel_launch(void* const* d_in, const int* in_sizes, int n_in,
                              void* d_out, int out_size) {
    const float* x   = (const float*)d_in[0];
    const float* Phi = (const float*)d_in[1];
    if (n_in >= 2 && in_sizes[0] == OUT_DIM * IN_DIM &&
        in_sizes[1] == N_ROWS * IN_DIM) {
        x   = (const float*)d_in[1];
        Phi = (const float*)d_in[0];
    }
    float* out = (float*)d_out;

    build_csr<<<OUT_DIM / 8, 256>>>(Phi);

    cudaFuncSetAttribute(jl_main, cudaFuncAttributeMaxDynamicSharedMemorySize,
                         SMEM_BYTES);
    jl_main<<<N_ROWS / TILE_N, THREADS, SMEM_BYTES>>>(x, out);
}